// round 9
// baseline (speedup 1.0000x reference)
#include <cuda_runtime.h>
#include <cstdint>

#define N_NODES 100000
#define D_FEAT  256
#define ATT     256
#define NSPLIT  24            // 3125 K-tiles of 32 rows split 24 ways

#define SA 20                 // u32 stride of A rows (16 f16x2 used)
#define SB 20                 // u32 stride of B rows (16 f16x2 used)
#define A_U32 (128 * SA)      // 2560 u32
#define B_U32 (256 * SB)      // 5120 u32
#define STAGE_U32 (A_U32 + B_U32)        // 7680 u32 = 30720 B
#define SMEM_TOTAL (2 * STAGE_U32 * 4)   // 61440 B

// Scratch (allocation-free)
__device__ float T_dev[3 * ATT * D_FEAT];
__device__ float beta_dev[3 * D_FEAT];

__device__ __forceinline__ uint32_t packf16(float lo, float hi) {
    uint32_t d;
    asm("cvt.rn.f16x2.f32 %0, %1, %2;" : "=r"(d) : "f"(hi), "f"(lo));  // first src -> high half
    return d;
}

__global__ void zeroT_kernel() {
    int i = blockIdx.x * blockDim.x + threadIdx.x;
    if (i < 3 * ATT * D_FEAT) T_dev[i] = 0.0f;
}

// grid (6 combos: v x mt, 24 K-splits), 512 threads = 16 warps (2 Mwarp x 8 Nwarp).
// CTA tile 128(M) x 256(N), warp tile 64x32, mma m16n8k16 f16 (f32 accum).
__global__ __launch_bounds__(512, 1)
void gemm_mma_kernel(const float* __restrict__ x1,
                     const float* __restrict__ x2,
                     const float* __restrict__ x3,
                     const float* __restrict__ W)
{
    extern __shared__ __align__(16) uint32_t smem[];

    const int bx = blockIdx.x;
    const int v  = bx >> 1;
    const int mt = bx & 1;
    const float* __restrict__ X = (v == 0) ? x1 : ((v == 1) ? x2 : x3);
    const int m0 = mt * 128;

    const int split  = blockIdx.y;
    const int tstart = split * 130 + min(split, 5);   // 3125 = 24*130 + 5
    const int NT     = 130 + (split < 5 ? 1 : 0);

    const int tid  = threadIdx.x;
    const int lane = tid & 31;
    const int w    = tid >> 5;
    const int wm   = w & 1;        // 0/1 -> 64 M-rows
    const int wn   = w >> 1;       // 0..7 -> 32 N-cols
    const int g    = lane >> 2;    // groupID (0..7)
    const int tig  = lane & 3;     // thread-in-group

    float acc[4][4][4];
    #pragma unroll
    for (int i = 0; i < 4; i++)
        #pragma unroll
        for (int j = 0; j < 4; j++)
            #pragma unroll
            for (int r = 0; r < 4; r++) acc[i][j][r] = 0.0f;

    // ---- staging maps ----
    // A: one unit/thread: row am (0..127), k-chunk 8*ac8
    const int am  = tid >> 2, ac8 = tid & 3;
    // B: two units/thread: flat = u*512+tid -> k-pair bkp (0..15), n-group bng (0..63)
    const int bkp0 = tid & 15;                 // same for both units
    const int bng0 = tid >> 4;                 // unit u adds 32

    float4 a4[2];        // A LDG regs (8 f32)
    float4 b4[2][2];     // B LDG regs (2 units x 2 k-rows x float4)

    auto ldg_tile = [&](int tt) {
        const int k0 = (tstart + tt) * 32;
        const float* wrow = W + (size_t)(m0 + am) * N_NODES + k0 + 8 * ac8;
        a4[0] = *reinterpret_cast<const float4*>(wrow);
        a4[1] = *reinterpret_cast<const float4*>(wrow + 4);
        #pragma unroll
        for (int u = 0; u < 2; u++) {
            const int kk = k0 + 2 * bkp0;
            const int nb = 4 * (bng0 + u * 32);
            b4[u][0] = *reinterpret_cast<const float4*>(X + (size_t)kk * D_FEAT + nb);
            b4[u][1] = *reinterpret_cast<const float4*>(X + (size_t)(kk + 1) * D_FEAT + nb);
        }
    };

    auto sts_tile = [&](int s) {
        uint32_t* As = smem + s * STAGE_U32;
        uint32_t* Bs = As + A_U32;
        // A: pack 4 k-pairs, one STS.128
        uint4 pa;
        pa.x = packf16(a4[0].x, a4[0].y);
        pa.y = packf16(a4[0].z, a4[0].w);
        pa.z = packf16(a4[1].x, a4[1].y);
        pa.w = packf16(a4[1].z, a4[1].w);
        *reinterpret_cast<uint4*>(&As[am * SA + 4 * ac8]) = pa;
        // B: transpose-in-register -> n-major rows, k-pair columns (conflict-free STS.32)
        #pragma unroll
        for (int u = 0; u < 2; u++) {
            const int nb = 4 * (bng0 + u * 32);
            const float* e = reinterpret_cast<const float*>(&b4[u][0]);
            const float* o = reinterpret_cast<const float*>(&b4[u][1]);
            #pragma unroll
            for (int j = 0; j < 4; j++)
                Bs[(nb + j) * SB + bkp0] = packf16(e[j], o[j]);
        }
    };

    // prologue: tile 0 into stage 0
    ldg_tile(0);
    sts_tile(0);
    __syncthreads();

    for (int t = 0; t < NT; t++) {
        const bool more = (t + 1 < NT);
        if (more) ldg_tile(t + 1);

        const uint32_t* As = smem + (t & 1) * STAGE_U32;
        const uint32_t* Bs = As + A_U32;

        #pragma unroll
        for (int kk = 0; kk < 2; kk++) {
            uint32_t a[4][4], b[4][2];
            #pragma unroll
            for (int fm = 0; fm < 4; fm++) {
                int m = wm * 64 + fm * 16 + g;
                int c = kk * 8 + tig;
                a[fm][0] = As[m * SA + c];
                a[fm][1] = As[(m + 8) * SA + c];
                a[fm][2] = As[m * SA + c + 4];
                a[fm][3] = As[(m + 8) * SA + c + 4];
            }
            #pragma unroll
            for (int fn = 0; fn < 4; fn++) {
                int n = wn * 32 + fn * 8 + g;
                b[fn][0] = Bs[n * SB + kk * 8 + tig];
                b[fn][1] = Bs[n * SB + kk * 8 + tig + 4];
            }
            #pragma unroll
            for (int fm = 0; fm < 4; fm++)
                #pragma unroll
                for (int fn = 0; fn < 4; fn++)
                    asm volatile(
                        "mma.sync.aligned.m16n8k16.row.col.f32.f16.f16.f32 "
                        "{%0,%1,%2,%3}, {%4,%5,%6,%7}, {%8,%9}, {%0,%1,%2,%3};"
                        : "+f"(acc[fm][fn][0]), "+f"(acc[fm][fn][1]),
                          "+f"(acc[fm][fn][2]), "+f"(acc[fm][fn][3])
                        : "r"(a[fm][0]), "r"(a[fm][1]), "r"(a[fm][2]), "r"(a[fm][3]),
                          "r"(b[fn][0]), "r"(b[fn][1]));
        }

        if (more) sts_tile((t + 1) & 1);
        __syncthreads();
    }

    // accumulate partials into global T
    float* Tg = &T_dev[v * ATT * D_FEAT];
    #pragma unroll
    for (int fm = 0; fm < 4; fm++) {
        int mrow = m0 + wm * 64 + fm * 16 + g;
        #pragma unroll
        for (int fn = 0; fn < 4; fn++) {
            int ncol = wn * 32 + fn * 8 + 2 * tig;
            atomicAdd(&Tg[mrow * D_FEAT + ncol],           acc[fm][fn][0]);
            atomicAdd(&Tg[mrow * D_FEAT + ncol + 1],       acc[fm][fn][1]);
            atomicAdd(&Tg[(mrow + 8) * D_FEAT + ncol],     acc[fm][fn][2]);
            atomicAdd(&Tg[(mrow + 8) * D_FEAT + ncol + 1], acc[fm][fn][3]);
        }
    }
}

// grid 8 x 256 threads: 32 d-columns per block, 8 K-chunks per column.
__global__ void finalize_kernel(const float* __restrict__ hn) {
    __shared__ float hs[ATT];
    __shared__ float red[3][8][32];
    int tid = threadIdx.x;
    hs[tid] = hn[tid];
    __syncthreads();

    int dl = tid & 31, ch = tid >> 5;
    int d  = blockIdx.x * 32 + dl;
    #pragma unroll
    for (int v = 0; v < 3; v++) {
        const float* Tg = &T_dev[v * ATT * D_FEAT];
        float a = 0.0f;
        #pragma unroll 8
        for (int i = ch * 32; i < ch * 32 + 32; i++)
            a += hs[i] * tanhf(Tg[i * D_FEAT + d]);
        red[v][ch][dl] = a;
    }
    __syncthreads();
    if (ch == 0) {
        float s[3];
        #pragma unroll
        for (int v = 0; v < 3; v++) {
            float a = 0.0f;
            #pragma unroll
            for (int c = 0; c < 8; c++) a += red[v][c][dl];
            s[v] = a;
        }
        float m  = fmaxf(s[0], fmaxf(s[1], s[2]));
        float e0 = expf(s[0] - m), e1 = expf(s[1] - m), e2 = expf(s[2] - m);
        float inv = 1.0f / (e0 + e1 + e2);
        beta_dev[0 * D_FEAT + d] = e0 * inv;
        beta_dev[1 * D_FEAT + d] = e1 * inv;
        beta_dev[2 * D_FEAT + d] = e2 * inv;
    }
}

// Streaming weighted sum: out[n,d] = b0[d]*x1 + b1[d]*x2 + b2[d]*x3 (float4)
__global__ void weighted_kernel(const float4* __restrict__ x1,
                                const float4* __restrict__ x2,
                                const float4* __restrict__ x3,
                                float4* __restrict__ out)
{
    __shared__ __align__(16) float b[3 * D_FEAT];
    b[threadIdx.x]       = beta_dev[threadIdx.x];
    b[256 + threadIdx.x] = beta_dev[256 + threadIdx.x];
    b[512 + threadIdx.x] = beta_dev[512 + threadIdx.x];
    __syncthreads();

    long idx = (long)blockIdx.x * blockDim.x + threadIdx.x;
    if (idx >= (long)N_NODES * D_FEAT / 4) return;
    int c = (int)(idx & 63);

    const float4* bf = reinterpret_cast<const float4*>(b);
    float4 B0 = bf[c], B1 = bf[64 + c], B2 = bf[128 + c];
    float4 v1 = x1[idx], v2 = x2[idx], v3 = x3[idx];

    float4 o;
    o.x = B0.x * v1.x + B1.x * v2.x + B2.x * v3.x;
    o.y = B0.y * v1.y + B1.y * v2.y + B2.y * v3.y;
    o.z = B0.z * v1.z + B1.z * v2.z + B2.z * v3.z;
    o.w = B0.w * v1.w + B1.w * v2.w + B2.w * v3.w;
    out[idx] = o;
}

extern "C" void kernel_launch(void* const* d_in, const int* in_sizes, int n_in,
                              void* d_out, int out_size)
{
    const float* x1 = (const float*)d_in[0];
    const float* x2 = (const float*)d_in[1];
    const float* x3 = (const float*)d_in[2];
    const float* W  = (const float*)d_in[3];
    const float* hn = (const float*)d_in[4];

    cudaFuncSetAttribute(gemm_mma_kernel, cudaFuncAttributeMaxDynamicSharedMemorySize, SMEM_TOTAL);

    zeroT_kernel<<<192, 1024>>>();
    gemm_mma_kernel<<<dim3(6, NSPLIT), 512, SMEM_TOTAL>>>(x1, x2, x3, W);
    finalize_kernel<<<8, 256>>>(hn);
    weighted_kernel<<<25000, 256>>>((const float4*)x1, (const float4*)x2,
                                    (const float4*)x3, (float4*)d_out);
}

// round 10
// speedup vs baseline: 1.6809x; 1.6809x over previous
#include <cuda_runtime.h>
#include <cstdint>

#define N_NODES 100000
#define D_FEAT  256
#define ATT     256
#define NSPLIT  24            // 3125 K-tiles of 32 rows split 24 ways

#define SA  20                // A f16 row stride in u32 (16 used)
#define SBK 132               // B f16 k-major row stride in u32 (128 used)
#define A_U32 (128 * SA)      // 2560
#define B_U32 (32 * SBK)      // 4224
#define STAGE_U32 (A_U32 + B_U32)        // 6784 u32 = 27136 B
#define SMEM_TOTAL (2 * STAGE_U32 * 4)   // 54272 B

// Scratch (allocation-free)
__device__ float T_dev[3 * ATT * D_FEAT];
__device__ float beta_dev[3 * D_FEAT];

__device__ __forceinline__ uint32_t smem_u32(const void* p) {
    uint32_t a;
    asm("{ .reg .u64 t; cvta.to.shared.u64 t, %1; cvt.u32.u64 %0, t; }" : "=r"(a) : "l"(p));
    return a;
}
__device__ __forceinline__ uint32_t packf16(float lo, float hi) {
    uint32_t d;
    asm("cvt.rn.f16x2.f32 %0, %1, %2;" : "=r"(d) : "f"(hi), "f"(lo));  // first src -> high half
    return d;
}
__device__ __forceinline__ void ldmx4t(uint32_t& r0, uint32_t& r1, uint32_t& r2, uint32_t& r3,
                                       uint32_t addr) {
    asm volatile("ldmatrix.sync.aligned.m8n8.x4.trans.shared.b16 {%0,%1,%2,%3}, [%4];"
                 : "=r"(r0), "=r"(r1), "=r"(r2), "=r"(r3) : "r"(addr));
}

__global__ void zeroT_kernel() {
    int i = blockIdx.x * blockDim.x + threadIdx.x;
    if (i < 3 * ATT * D_FEAT) T_dev[i] = 0.0f;
}

// grid (6 combos: v x mt, 24 K-splits), 512 threads = 16 warps (2 Mwarp x 8 Nwarp).
// CTA tile 128(M) x 256(N), warp tile 64x32, mma m16n8k16 f16 (f32 accum).
__global__ __launch_bounds__(512, 1)
void gemm_mma_kernel(const float* __restrict__ x1,
                     const float* __restrict__ x2,
                     const float* __restrict__ x3,
                     const float* __restrict__ W)
{
    extern __shared__ __align__(16) uint32_t smem[];
    const uint32_t sb = smem_u32(smem);

    const int bx = blockIdx.x;
    const int v  = bx >> 1;
    const int mt = bx & 1;
    const float* __restrict__ X = (v == 0) ? x1 : ((v == 1) ? x2 : x3);
    const int m0 = mt * 128;

    const int split  = blockIdx.y;
    const int tstart = split * 130 + min(split, 5);   // 3125 = 24*130 + 5
    const int NT     = 130 + (split < 5 ? 1 : 0);

    const int tid  = threadIdx.x;
    const int lane = tid & 31;
    const int w    = tid >> 5;
    const int wm   = w & 1;        // 0/1 -> 64 M-rows
    const int wn   = w >> 1;       // 0..7 -> 32 N-cols
    const int g    = lane >> 2;    // groupID (0..7)
    const int tig  = lane & 3;     // thread-in-group

    float acc[4][4][4];
    #pragma unroll
    for (int i = 0; i < 4; i++)
        #pragma unroll
        for (int j = 0; j < 4; j++)
            #pragma unroll
            for (int r = 0; r < 4; r++) acc[i][j][r] = 0.0f;

    // ---- staging maps (all coalesced) ----
    // A: row am (0..127), 8-float chunk ac8 (0..3)
    const int am  = tid >> 2, ac8 = tid & 3;
    // B: base row j0 (0..7) + 8*i, float4 chunk c0 (0..63): warp = half row, contiguous
    const int bj0 = tid >> 6, bc0 = tid & 63;

    float4 a4[2];        // A LDG regs
    float4 b4[4];        // B LDG regs (4 rows)

    auto ldg_tile = [&](int tt) {
        const int k0 = (tstart + tt) * 32;
        const float* wrow = W + (size_t)(m0 + am) * N_NODES + k0 + 8 * ac8;
        a4[0] = *reinterpret_cast<const float4*>(wrow);
        a4[1] = *reinterpret_cast<const float4*>(wrow + 4);
        #pragma unroll
        for (int i = 0; i < 4; i++)
            b4[i] = *reinterpret_cast<const float4*>(
                X + (size_t)(k0 + bj0 + 8 * i) * D_FEAT + 4 * bc0);
    };

    auto sts_tile = [&](int s) {
        uint32_t* As = smem + s * STAGE_U32;
        uint32_t* Bs = As + A_U32;
        uint4 pa;
        pa.x = packf16(a4[0].x, a4[0].y);
        pa.y = packf16(a4[0].z, a4[0].w);
        pa.z = packf16(a4[1].x, a4[1].y);
        pa.w = packf16(a4[1].z, a4[1].w);
        *reinterpret_cast<uint4*>(&As[am * SA + 4 * ac8]) = pa;
        #pragma unroll
        for (int i = 0; i < 4; i++) {
            uint2 pb;
            pb.x = packf16(b4[i].x, b4[i].y);
            pb.y = packf16(b4[i].z, b4[i].w);
            *reinterpret_cast<uint2*>(&Bs[(bj0 + 8 * i) * SBK + 2 * bc0]) = pb;
        }
    };

    // B ldmatrix lane addressing: group q = lane>>3 (q&1: k half, q>>1: n half), i = lane&7
    const int lq = lane >> 3, li = lane & 7;

    ldg_tile(0);
    sts_tile(0);
    __syncthreads();

    for (int t = 0; t < NT; t++) {
        const bool more = (t + 1 < NT);
        if (more) ldg_tile(t + 1);

        const uint32_t a_off = (t & 1) * STAGE_U32 * 4;
        const uint32_t* As = smem + (t & 1) * STAGE_U32;
        const uint32_t b_base = sb + a_off + A_U32 * 4;

        #pragma unroll
        for (int kk = 0; kk < 2; kk++) {
            uint32_t a[4][4], b[4][2];
            #pragma unroll
            for (int fm = 0; fm < 4; fm++) {
                int m = wm * 64 + fm * 16 + g;
                int c = kk * 8 + tig;
                a[fm][0] = As[m * SA + c];
                a[fm][1] = As[(m + 8) * SA + c];
                a[fm][2] = As[m * SA + c + 4];
                a[fm][3] = As[(m + 8) * SA + c + 4];
            }
            #pragma unroll
            for (int fnp = 0; fnp < 2; fnp++) {
                // rows k = kk*16 + (q&1)*8 + i ; cols n = wn*32 + fnp*16 + (q>>1)*8
                int krow = kk * 16 + (lq & 1) * 8 + li;
                int ncol = wn * 32 + fnp * 16 + (lq >> 1) * 8;
                uint32_t addr = b_base + (krow * SBK + (ncol >> 1)) * 4;
                ldmx4t(b[2 * fnp][0], b[2 * fnp][1],
                       b[2 * fnp + 1][0], b[2 * fnp + 1][1], addr);
            }
            #pragma unroll
            for (int fm = 0; fm < 4; fm++)
                #pragma unroll
                for (int fn = 0; fn < 4; fn++)
                    asm volatile(
                        "mma.sync.aligned.m16n8k16.row.col.f32.f16.f16.f32 "
                        "{%0,%1,%2,%3}, {%4,%5,%6,%7}, {%8,%9}, {%0,%1,%2,%3};"
                        : "+f"(acc[fm][fn][0]), "+f"(acc[fm][fn][1]),
                          "+f"(acc[fm][fn][2]), "+f"(acc[fm][fn][3])
                        : "r"(a[fm][0]), "r"(a[fm][1]), "r"(a[fm][2]), "r"(a[fm][3]),
                          "r"(b[fn][0]), "r"(b[fn][1]));
        }

        if (more) sts_tile((t + 1) & 1);
        __syncthreads();
    }

    // accumulate partials into global T
    float* Tg = &T_dev[v * ATT * D_FEAT];
    #pragma unroll
    for (int fm = 0; fm < 4; fm++) {
        int mrow = m0 + wm * 64 + fm * 16 + g;
        #pragma unroll
        for (int fn = 0; fn < 4; fn++) {
            int ncol = wn * 32 + fn * 8 + 2 * tig;
            atomicAdd(&Tg[mrow * D_FEAT + ncol],           acc[fm][fn][0]);
            atomicAdd(&Tg[mrow * D_FEAT + ncol + 1],       acc[fm][fn][1]);
            atomicAdd(&Tg[(mrow + 8) * D_FEAT + ncol],     acc[fm][fn][2]);
            atomicAdd(&Tg[(mrow + 8) * D_FEAT + ncol + 1], acc[fm][fn][3]);
        }
    }
}

// grid 8 x 256 threads: 32 d-columns per block, 8 K-chunks per column.
__global__ void finalize_kernel(const float* __restrict__ hn) {
    __shared__ float hs[ATT];
    __shared__ float red[3][8][32];
    int tid = threadIdx.x;
    hs[tid] = hn[tid];
    __syncthreads();

    int dl = tid & 31, ch = tid >> 5;
    int d  = blockIdx.x * 32 + dl;
    #pragma unroll
    for (int v = 0; v < 3; v++) {
        const float* Tg = &T_dev[v * ATT * D_FEAT];
        float a = 0.0f;
        #pragma unroll 8
        for (int i = ch * 32; i < ch * 32 + 32; i++)
            a += hs[i] * tanhf(Tg[i * D_FEAT + d]);
        red[v][ch][dl] = a;
    }
    __syncthreads();
    if (ch == 0) {
        float s[3];
        #pragma unroll
        for (int v = 0; v < 3; v++) {
            float a = 0.0f;
            #pragma unroll
            for (int c = 0; c < 8; c++) a += red[v][c][dl];
            s[v] = a;
        }
        float m  = fmaxf(s[0], fmaxf(s[1], s[2]));
        float e0 = expf(s[0] - m), e1 = expf(s[1] - m), e2 = expf(s[2] - m);
        float inv = 1.0f / (e0 + e1 + e2);
        beta_dev[0 * D_FEAT + d] = e0 * inv;
        beta_dev[1 * D_FEAT + d] = e1 * inv;
        beta_dev[2 * D_FEAT + d] = e2 * inv;
    }
}

// Streaming weighted sum: out[n,d] = b0[d]*x1 + b1[d]*x2 + b2[d]*x3 (float4)
__global__ void weighted_kernel(const float4* __restrict__ x1,
                                const float4* __restrict__ x2,
                                const float4* __restrict__ x3,
                                float4* __restrict__ out)
{
    __shared__ __align__(16) float b[3 * D_FEAT];
    b[threadIdx.x]       = beta_dev[threadIdx.x];
    b[256 + threadIdx.x] = beta_dev[256 + threadIdx.x];
    b[512 + threadIdx.x] = beta_dev[512 + threadIdx.x];
    __syncthreads();

    long idx = (long)blockIdx.x * blockDim.x + threadIdx.x;
    if (idx >= (long)N_NODES * D_FEAT / 4) return;
    int c = (int)(idx & 63);

    const float4* bf = reinterpret_cast<const float4*>(b);
    float4 B0 = bf[c], B1 = bf[64 + c], B2 = bf[128 + c];
    float4 v1 = x1[idx], v2 = x2[idx], v3 = x3[idx];

    float4 o;
    o.x = B0.x * v1.x + B1.x * v2.x + B2.x * v3.x;
    o.y = B0.y * v1.y + B1.y * v2.y + B2.y * v3.y;
    o.z = B0.z * v1.z + B1.z * v2.z + B2.z * v3.z;
    o.w = B0.w * v1.w + B1.w * v2.w + B2.w * v3.w;
    out[idx] = o;
}

extern "C" void kernel_launch(void* const* d_in, const int* in_sizes, int n_in,
                              void* d_out, int out_size)
{
    const float* x1 = (const float*)d_in[0];
    const float* x2 = (const float*)d_in[1];
    const float* x3 = (const float*)d_in[2];
    const float* W  = (const float*)d_in[3];
    const float* hn = (const float*)d_in[4];

    cudaFuncSetAttribute(gemm_mma_kernel, cudaFuncAttributeMaxDynamicSharedMemorySize, SMEM_TOTAL);

    zeroT_kernel<<<192, 1024>>>();
    gemm_mma_kernel<<<dim3(6, NSPLIT), 512, SMEM_TOTAL>>>(x1, x2, x3, W);
    finalize_kernel<<<8, 256>>>(hn);
    weighted_kernel<<<25000, 256>>>((const float4*)x1, (const float4*)x2,
                                    (const float4*)x3, (float4*)d_out);
}

// round 12
// speedup vs baseline: 1.7601x; 1.0471x over previous
#include <cuda_runtime.h>
#include <cstdint>

#define N_NODES 100000
#define D_FEAT  256
#define ATT     256
#define NSPLIT  24            // 3125 K-tiles of 32 rows split 24 ways

#define SA  20                // A f16 row stride in u32 (16 used)
#define SBK 132               // B f16 k-major row stride in u32 (128 used)
#define A_U32 (128 * SA)      // 2560
#define B_U32 (32 * SBK)      // 4224
#define STAGE_U32 (A_U32 + B_U32)        // 6784 u32 = 27136 B
#define SMEM_TOTAL (2 * STAGE_U32 * 4)   // 54272 B

// Scratch (allocation-free)
__device__ float T_dev[3 * ATT * D_FEAT];
__device__ float beta_dev[3 * D_FEAT];

__device__ __forceinline__ uint32_t smem_u32(const void* p) {
    uint32_t a;
    asm("{ .reg .u64 t; cvta.to.shared.u64 t, %1; cvt.u32.u64 %0, t; }" : "=r"(a) : "l"(p));
    return a;
}
__device__ __forceinline__ uint32_t packf16(float lo, float hi) {
    uint32_t d;
    asm("cvt.rn.f16x2.f32 %0, %1, %2;" : "=r"(d) : "f"(hi), "f"(lo));  // first src -> high half
    return d;
}
__device__ __forceinline__ void ldmx4(uint32_t& r0, uint32_t& r1, uint32_t& r2, uint32_t& r3,
                                      uint32_t addr) {
    asm volatile("ldmatrix.sync.aligned.m8n8.x4.shared.b16 {%0,%1,%2,%3}, [%4];"
                 : "=r"(r0), "=r"(r1), "=r"(r2), "=r"(r3) : "r"(addr));
}
__device__ __forceinline__ void ldmx4t(uint32_t& r0, uint32_t& r1, uint32_t& r2, uint32_t& r3,
                                       uint32_t addr) {
    asm volatile("ldmatrix.sync.aligned.m8n8.x4.trans.shared.b16 {%0,%1,%2,%3}, [%4];"
                 : "=r"(r0), "=r"(r1), "=r"(r2), "=r"(r3) : "r"(addr));
}

__global__ void zeroT_kernel() {
    int i = blockIdx.x * blockDim.x + threadIdx.x;
    if (i < 3 * ATT * D_FEAT) T_dev[i] = 0.0f;
}

// grid (6 combos: v x mt, 24 K-splits), 512 threads = 16 warps (2 Mwarp x 8 Nwarp).
// CTA tile 128(M) x 256(N), warp tile 64x32, mma m16n8k16 f16 (f32 accum).
__global__ __launch_bounds__(512, 1)
void gemm_mma_kernel(const float* __restrict__ x1,
                     const float* __restrict__ x2,
                     const float* __restrict__ x3,
                     const float* __restrict__ W)
{
    extern __shared__ __align__(16) uint32_t smem[];
    const uint32_t sb = smem_u32(smem);

    const int bx = blockIdx.x;
    const int v  = bx >> 1;
    const int mt = bx & 1;
    const float* __restrict__ X = (v == 0) ? x1 : ((v == 1) ? x2 : x3);
    const int m0 = mt * 128;

    const int split  = blockIdx.y;
    const int tstart = split * 130 + min(split, 5);   // 3125 = 24*130 + 5
    const int NT     = 130 + (split < 5 ? 1 : 0);

    const int tid  = threadIdx.x;
    const int lane = tid & 31;
    const int w    = tid >> 5;
    const int wm   = w & 1;        // 0/1 -> 64 M-rows
    const int wn   = w >> 1;       // 0..7 -> 32 N-cols
    const int g    = lane >> 2;    // groupID (0..7)
    const int tig  = lane & 3;     // thread-in-group

    float acc[4][4][4];
    #pragma unroll
    for (int i = 0; i < 4; i++)
        #pragma unroll
        for (int j = 0; j < 4; j++)
            #pragma unroll
            for (int r = 0; r < 4; r++) acc[i][j][r] = 0.0f;

    // ---- staging maps (all coalesced) ----
    const int am  = tid >> 2, ac8 = tid & 3;   // A: row, 8-float chunk
    const int bj0 = tid >> 6, bc0 = tid & 63;  // B: base k-row, float4 chunk

    float4 a4[2];
    float4 b4[4];

    auto ldg_tile = [&](int tt) {
        const int k0 = (tstart + tt) * 32;
        const float* wrow = W + (size_t)(m0 + am) * N_NODES + k0 + 8 * ac8;
        a4[0] = *reinterpret_cast<const float4*>(wrow);
        a4[1] = *reinterpret_cast<const float4*>(wrow + 4);
        #pragma unroll
        for (int i = 0; i < 4; i++)
            b4[i] = *reinterpret_cast<const float4*>(
                X + (size_t)(k0 + bj0 + 8 * i) * D_FEAT + 4 * bc0);
    };

    auto sts_tile = [&](int s) {
        uint32_t* As = smem + s * STAGE_U32;
        uint32_t* Bs = As + A_U32;
        uint4 pa;
        pa.x = packf16(a4[0].x, a4[0].y);
        pa.y = packf16(a4[0].z, a4[0].w);
        pa.z = packf16(a4[1].x, a4[1].y);
        pa.w = packf16(a4[1].z, a4[1].w);
        *reinterpret_cast<uint4*>(&As[am * SA + 4 * ac8]) = pa;
        #pragma unroll
        for (int i = 0; i < 4; i++) {
            uint2 pb;
            pb.x = packf16(b4[i].x, b4[i].y);
            pb.y = packf16(b4[i].z, b4[i].w);
            *reinterpret_cast<uint2*>(&Bs[(bj0 + 8 * i) * SBK + 2 * bc0]) = pb;
        }
    };

    // ldmatrix lane addressing
    const int a_row  = lane & 15;            // row within 16-row block
    const int a_colh = (lane >> 4) << 2;     // u32 col offset 0 or 4 (k-pair half)
    const int lq = lane >> 3, li = lane & 7; // B: quad + index

    ldg_tile(0);
    sts_tile(0);
    __syncthreads();

    for (int t = 0; t < NT; t++) {
        const bool more = (t + 1 < NT);
        if (more) ldg_tile(t + 1);

        const uint32_t st_byte = (t & 1) * (STAGE_U32 * 4);
        const uint32_t a_base = sb + st_byte;
        const uint32_t b_base = a_base + A_U32 * 4;

        // ---- load ALL fragments for both kk steps, then run MMAs ----
        uint32_t a[2][4][4], b[2][4][2];
        #pragma unroll
        for (int kk = 0; kk < 2; kk++) {
            #pragma unroll
            for (int fm = 0; fm < 4; fm++) {
                int mrow = wm * 64 + fm * 16 + a_row;
                uint32_t addr = a_base + (mrow * SA + kk * 8 + a_colh) * 4;
                ldmx4(a[kk][fm][0], a[kk][fm][1], a[kk][fm][2], a[kk][fm][3], addr);
            }
            #pragma unroll
            for (int fnp = 0; fnp < 2; fnp++) {
                int krow = kk * 16 + (lq & 1) * 8 + li;
                int ncol = wn * 32 + fnp * 16 + (lq >> 1) * 8;
                uint32_t addr = b_base + (krow * SBK + (ncol >> 1)) * 4;
                ldmx4t(b[kk][2 * fnp][0], b[kk][2 * fnp][1],
                       b[kk][2 * fnp + 1][0], b[kk][2 * fnp + 1][1], addr);
            }
        }
        #pragma unroll
        for (int kk = 0; kk < 2; kk++)
            #pragma unroll
            for (int fm = 0; fm < 4; fm++)
                #pragma unroll
                for (int fn = 0; fn < 4; fn++)
                    asm volatile(
                        "mma.sync.aligned.m16n8k16.row.col.f32.f16.f16.f32 "
                        "{%0,%1,%2,%3}, {%4,%5,%6,%7}, {%8,%9}, {%0,%1,%2,%3};"
                        : "+f"(acc[fm][fn][0]), "+f"(acc[fm][fn][1]),
                          "+f"(acc[fm][fn][2]), "+f"(acc[fm][fn][3])
                        : "r"(a[kk][fm][0]), "r"(a[kk][fm][1]),
                          "r"(a[kk][fm][2]), "r"(a[kk][fm][3]),
                          "r"(b[kk][fn][0]), "r"(b[kk][fn][1]));

        if (more) sts_tile((t + 1) & 1);
        __syncthreads();
    }

    // accumulate partials into global T
    float* Tg = &T_dev[v * ATT * D_FEAT];
    #pragma unroll
    for (int fm = 0; fm < 4; fm++) {
        int mrow = m0 + wm * 64 + fm * 16 + g;
        #pragma unroll
        for (int fn = 0; fn < 4; fn++) {
            int ncol = wn * 32 + fn * 8 + 2 * tig;
            atomicAdd(&Tg[mrow * D_FEAT + ncol],           acc[fm][fn][0]);
            atomicAdd(&Tg[mrow * D_FEAT + ncol + 1],       acc[fm][fn][1]);
            atomicAdd(&Tg[(mrow + 8) * D_FEAT + ncol],     acc[fm][fn][2]);
            atomicAdd(&Tg[(mrow + 8) * D_FEAT + ncol + 1], acc[fm][fn][3]);
        }
    }
}

// grid 8 x 256 threads: 32 d-columns per block, 8 K-chunks per column.
__global__ void finalize_kernel(const float* __restrict__ hn) {
    __shared__ float hs[ATT];
    __shared__ float red[3][8][32];
    int tid = threadIdx.x;
    hs[tid] = hn[tid];
    __syncthreads();

    int dl = tid & 31, ch = tid >> 5;
    int d  = blockIdx.x * 32 + dl;
    #pragma unroll
    for (int v = 0; v < 3; v++) {
        const float* Tg = &T_dev[v * ATT * D_FEAT];
        float a = 0.0f;
        #pragma unroll 8
        for (int i = ch * 32; i < ch * 32 + 32; i++)
            a += hs[i] * tanhf(Tg[i * D_FEAT + d]);
        red[v][ch][dl] = a;
    }
    __syncthreads();
    if (ch == 0) {
        float s[3];
        #pragma unroll
        for (int v = 0; v < 3; v++) {
            float a = 0.0f;
            #pragma unroll
            for (int c = 0; c < 8; c++) a += red[v][c][dl];
            s[v] = a;
        }
        float m  = fmaxf(s[0], fmaxf(s[1], s[2]));
        float e0 = expf(s[0] - m), e1 = expf(s[1] - m), e2 = expf(s[2] - m);
        float inv = 1.0f / (e0 + e1 + e2);
        beta_dev[0 * D_FEAT + d] = e0 * inv;
        beta_dev[1 * D_FEAT + d] = e1 * inv;
        beta_dev[2 * D_FEAT + d] = e2 * inv;
    }
}

// Streaming weighted sum: out[n,d] = b0[d]*x1 + b1[d]*x2 + b2[d]*x3 (float4)
__global__ void weighted_kernel(const float4* __restrict__ x1,
                                const float4* __restrict__ x2,
                                const float4* __restrict__ x3,
                                float4* __restrict__ out)
{
    __shared__ __align__(16) float b[3 * D_FEAT];
    b[threadIdx.x]       = beta_dev[threadIdx.x];
    b[256 + threadIdx.x] = beta_dev[256 + threadIdx.x];
    b[512 + threadIdx.x] = beta_dev[512 + threadIdx.x];
    __syncthreads();

    long idx = (long)blockIdx.x * blockDim.x + threadIdx.x;
    if (idx >= (long)N_NODES * D_FEAT / 4) return;
    int c = (int)(idx & 63);

    const float4* bf = reinterpret_cast<const float4*>(b);
    float4 B0 = bf[c], B1 = bf[64 + c], B2 = bf[128 + c];
    float4 v1 = x1[idx], v2 = x2[idx], v3 = x3[idx];

    float4 o;
    o.x = B0.x * v1.x + B1.x * v2.x + B2.x * v3.x;
    o.y = B0.y * v1.y + B1.y * v2.y + B2.y * v3.y;
    o.z = B0.z * v1.z + B1.z * v2.z + B2.z * v3.z;
    o.w = B0.w * v1.w + B1.w * v2.w + B2.w * v3.w;
    out[idx] = o;
}

extern "C" void kernel_launch(void* const* d_in, const int* in_sizes, int n_in,
                              void* d_out, int out_size)
{
    const float* x1 = (const float*)d_in[0];
    const float* x2 = (const float*)d_in[1];
    const float* x3 = (const float*)d_in[2];
    const float* W  = (const float*)d_in[3];
    const float* hn = (const float*)d_in[4];

    cudaFuncSetAttribute(gemm_mma_kernel, cudaFuncAttributeMaxDynamicSharedMemorySize, SMEM_TOTAL);

    zeroT_kernel<<<192, 1024>>>();
    gemm_mma_kernel<<<dim3(6, NSPLIT), 512, SMEM_TOTAL>>>(x1, x2, x3, W);
    finalize_kernel<<<8, 256>>>(hn);
    weighted_kernel<<<25000, 256>>>((const float4*)x1, (const float4*)x2,
                                    (const float4*)x3, (float4*)d_out);
}